// round 2
// baseline (speedup 1.0000x reference)
#include <cuda_runtime.h>
#include <math.h>
#include <stdint.h>

// Problem constants
#define BB 32
#define TT 64
#define EE 512
#define HH 512
#define VV 32000
#define NSTEP 63              // T-1 timesteps
#define MM (NSTEP * BB)       // 2016 rows
#define G4 (4 * HH)           // 2048 gate columns
#define KK 512

// -------------------- device scratch (no allocs allowed) --------------------
__device__ float g_xseq[MM * EE];          // [63*32][512]  LSTM inputs
__device__ float g_pre[(size_t)MM * G4];   // [2016][2048]  pre-gates (x@W_ih^T + biases)
__device__ float g_hs[MM * HH];            // [2016][512]   hidden states per step
__device__ float g_h[2][BB * HH];          // double-buffered h (cross-CTA race safety)
__device__ float g_c[BB * HH];             // cell state (CTA-private columns)
__device__ int   g_cap64;                  // 1 if captions buffer is int64

// -------------------- dtype detect for captions --------------------
__global__ void detect_cap64(const int* cap) {
    if (threadIdx.x == 0) {
        int f = 1;
        for (int i = 0; i < 32; i++)
            if (cap[2 * i + 1] != 0) { f = 0; break; }
        g_cap64 = f;
    }
}

// -------------------- init h/c to zero (every launch: graph-replay determinism) ----
__global__ void init_state() {
    int i = blockIdx.x * blockDim.x + threadIdx.x;
    if (i < BB * HH) { g_h[0][i] = 0.f; g_c[i] = 0.f; }
}

// -------------------- zero out[:, 0, :] --------------------
__global__ void zero_out0(float* out) {
    int b  = blockIdx.y;
    int vv = blockIdx.x * 256 + threadIdx.x;
    if (vv < VV) out[(size_t)b * TT * VV + vv] = 0.f;
}

// -------------------- build x_seq: [t=0]=features, [t>=1]=embed(captions[:,t+1]) ----
__global__ void build_xseq(const float* __restrict__ features,
                           const void*  __restrict__ cap,
                           const float* __restrict__ embed) {
    int i = blockIdx.x;   // 0..62
    int b = blockIdx.y;   // 0..31
    int col = threadIdx.x * 4;
    const float* src;
    if (i == 0) {
        src = features + (size_t)b * EE;
    } else {
        long long idx;
        if (g_cap64) idx = ((const long long*)cap)[b * TT + i + 1];
        else         idx = ((const int*)cap)[b * TT + i + 1];
        src = embed + (size_t)idx * EE;
    }
    *(float4*)&g_xseq[((size_t)i * BB + b) * EE + col] = *(const float4*)&src[col];
}

// -------------------- tf32 helpers --------------------
__device__ __forceinline__ uint32_t f2tf32(float x) {
    uint32_t u;
    asm("cvt.rna.tf32.f32 %0, %1;" : "=r"(u) : "f"(x));
    return u;
}

// -------------------- tf32 GEMM: out = A @ B^T + bias --------------------
// A row-major [M, 512] (device global picked by MODE), B row-major [N, 512].
// MODE 0: A=g_xseq, out=g_pre[m][n],              bias = bias1[n]+bias2[n]
// MODE 1: A=g_hs,   out=d_out[(b*64 + t+1)][n],   bias = bias1[n]   (m = t*32+b)
template <int MODE, int N>
__global__ void __launch_bounds__(256)
gemm_tf32(const float* __restrict__ Bmat,
          const float* __restrict__ bias1,
          const float* __restrict__ bias2,
          float* __restrict__ outc) {
    constexpr int BM = 128, BN = 64, BK = 16;
    __shared__ uint32_t sA[BM][BK + 4];
    __shared__ uint32_t sB[BN][BK + 4];

    const float* Amat = (MODE == 0) ? g_xseq : g_hs;
    float*       Out  = (MODE == 0) ? g_pre  : outc;

    int tid  = threadIdx.x;
    int wid  = tid >> 5, lane = tid & 31;
    int wm   = wid & 3,  wn   = wid >> 2;      // 4x2 warp grid, warp tile 32x32
    int grp  = lane >> 2, tig = lane & 3;
    int m0   = blockIdx.y * BM, n0 = blockIdx.x * BN;

    float c[2][4][4];
#pragma unroll
    for (int mi = 0; mi < 2; mi++)
#pragma unroll
        for (int ni = 0; ni < 4; ni++)
#pragma unroll
            for (int r = 0; r < 4; r++) c[mi][ni][r] = 0.f;

    for (int kt = 0; kt < KK / BK; kt++) {
        int k0 = kt * BK;
        // global -> regs
        float4 av[2]; int arow[2], acol[2];
#pragma unroll
        for (int l = 0; l < 2; l++) {
            int s = tid + l * 256;            // 0..511 float4 slots (128 rows x 4)
            int r = s >> 2, cq = s & 3;
            arow[l] = r; acol[l] = cq * 4;
            int gm = m0 + r;
            if (gm < MM) av[l] = *(const float4*)&Amat[(size_t)gm * KK + k0 + cq * 4];
            else         av[l] = make_float4(0.f, 0.f, 0.f, 0.f);
        }
        float4 bv;
        int br = tid >> 2, bc = (tid & 3) * 4; // 64 rows x 4 float4
        bv = *(const float4*)&Bmat[(size_t)(n0 + br) * KK + k0 + bc];

        __syncthreads();   // previous iter's compute done before overwrite
#pragma unroll
        for (int l = 0; l < 2; l++) {
            uint32_t* p = &sA[arow[l]][acol[l]];
            p[0] = f2tf32(av[l].x); p[1] = f2tf32(av[l].y);
            p[2] = f2tf32(av[l].z); p[3] = f2tf32(av[l].w);
        }
        {
            uint32_t* p = &sB[br][bc];
            p[0] = f2tf32(bv.x); p[1] = f2tf32(bv.y);
            p[2] = f2tf32(bv.z); p[3] = f2tf32(bv.w);
        }
        __syncthreads();

#pragma unroll
        for (int ks = 0; ks < 2; ks++) {
            int kk = ks * 8;
            uint32_t a[2][4], bf[4][2];
#pragma unroll
            for (int mi = 0; mi < 2; mi++) {
                int mr = wm * 32 + mi * 16;
                a[mi][0] = sA[mr + grp][kk + tig];
                a[mi][1] = sA[mr + grp + 8][kk + tig];
                a[mi][2] = sA[mr + grp][kk + tig + 4];
                a[mi][3] = sA[mr + grp + 8][kk + tig + 4];
            }
#pragma unroll
            for (int ni = 0; ni < 4; ni++) {
                int nr = wn * 32 + ni * 8;
                bf[ni][0] = sB[nr + grp][kk + tig];
                bf[ni][1] = sB[nr + grp][kk + tig + 4];
            }
#pragma unroll
            for (int mi = 0; mi < 2; mi++)
#pragma unroll
                for (int ni = 0; ni < 4; ni++) {
                    asm volatile(
                        "mma.sync.aligned.m16n8k8.row.col.f32.tf32.tf32.f32 "
                        "{%0,%1,%2,%3}, {%4,%5,%6,%7}, {%8,%9}, {%0,%1,%2,%3};"
                        : "+f"(c[mi][ni][0]), "+f"(c[mi][ni][1]),
                          "+f"(c[mi][ni][2]), "+f"(c[mi][ni][3])
                        : "r"(a[mi][0]), "r"(a[mi][1]), "r"(a[mi][2]), "r"(a[mi][3]),
                          "r"(bf[ni][0]), "r"(bf[ni][1]));
                }
        }
    }

    // epilogue
#pragma unroll
    for (int mi = 0; mi < 2; mi++) {
#pragma unroll
        for (int ni = 0; ni < 4; ni++) {
            int col = n0 + wn * 32 + ni * 8 + tig * 2;
            float bs0 = bias1[col]     + (MODE == 0 ? bias2[col]     : 0.f);
            float bs1 = bias1[col + 1] + (MODE == 0 ? bias2[col + 1] : 0.f);
#pragma unroll
            for (int half = 0; half < 2; half++) {
                int mrow = m0 + wm * 32 + mi * 16 + grp + half * 8;
                if (mrow < MM) {
                    size_t off;
                    if (MODE == 0) {
                        off = (size_t)mrow * N;
                    } else {
                        int t = mrow >> 5, b = mrow & 31;
                        off = ((size_t)(b * TT + t + 1)) * N;
                    }
                    Out[off + col]     = c[mi][ni][half * 2 + 0] + bs0;
                    Out[off + col + 1] = c[mi][ni][half * 2 + 1] + bs1;
                }
            }
        }
    }
}

// -------------------- LSTM step (fp32) --------------------
// grid 128 CTAs (4 hidden units each), 256 threads (8 warps).
// Warp w computes gate rows r = 2w, 2w+1 of this CTA's 16 gate rows,
// for all 32 batches (lane = batch). r = g*4 + du, j = g*512 + (cta*4+du).
#define LSTM_SMEM ((32 * 516 + 16 * 32) * 4)

__global__ void lstm_step(const float* __restrict__ Whh, int t) {
    extern __shared__ float sm[];
    float* shh = sm;             // [32][516] padded h (prev step)
    float* sg  = sm + 32 * 516;  // [16][32] gate values

    int tid = threadIdx.x;
    const float* hin = g_h[t & 1];
#pragma unroll
    for (int i = 0; i < 16; i++) {
        int s = tid + i * 256;           // 4096 float4 slots
        int row = s >> 7, c4 = s & 127;
        float4 v = *(const float4*)&hin[row * 512 + c4 * 4];
        *(float4*)&shh[row * 516 + c4 * 4] = v;
    }
    __syncthreads();

    int wid = tid >> 5, lane = tid & 31;
#pragma unroll
    for (int rr = 0; rr < 2; rr++) {
        int r = wid * 2 + rr;
        int gidx = r >> 2, du = r & 3;
        int u = blockIdx.x * 4 + du;
        int j = gidx * 512 + u;
        const float4* wp = (const float4*)(Whh + (size_t)j * 512);
        const float4* hp = (const float4*)&shh[lane * 516];
        float acc = 0.f;
#pragma unroll 4
        for (int kkk = 0; kkk < 128; kkk++) {
            float4 w4 = __ldg(&wp[kkk]);    // uniform across warp (broadcast)
            float4 h4 = hp[kkk];
            acc += w4.x * h4.x + w4.y * h4.y + w4.z * h4.z + w4.w * h4.w;
        }
        acc += g_pre[((size_t)t * 32 + lane) * (size_t)G4 + j];
        sg[r * 32 + lane] = acc;
    }
    __syncthreads();

    if (tid < 128) {
        int du = tid >> 5, b = tid & 31;
        int u  = blockIdx.x * 4 + du;
        float gi = sg[(0 + du) * 32 + b];
        float gf = sg[(4 + du) * 32 + b];
        float gg = sg[(8 + du) * 32 + b];
        float go = sg[(12 + du) * 32 + b];
        float si = 1.f / (1.f + __expf(-gi));
        float sf = 1.f / (1.f + __expf(-gf));
        float so = 1.f / (1.f + __expf(-go));
        float tg = tanhf(gg);
        float cn = sf * g_c[b * 512 + u] + si * tg;
        float hn = so * tanhf(cn);
        g_c[b * 512 + u] = cn;
        g_h[(t + 1) & 1][b * 512 + u] = hn;
        g_hs[((size_t)t * 32 + b) * 512 + u] = hn;
    }
}

// -------------------- launch --------------------
extern "C" void kernel_launch(void* const* d_in, const int* in_sizes, int n_in,
                              void* d_out, int out_size) {
    const float* features = (const float*)d_in[0];
    const void*  captions = d_in[1];
    const float* embed    = (const float*)d_in[2];
    const float* W_ih     = (const float*)d_in[3];
    const float* W_hh     = (const float*)d_in[4];
    const float* b_ih     = (const float*)d_in[5];
    const float* b_hh     = (const float*)d_in[6];
    const float* fc_w     = (const float*)d_in[7];
    const float* fc_b     = (const float*)d_in[8];
    float* out = (float*)d_out;

    cudaFuncSetAttribute(lstm_step, cudaFuncAttributeMaxDynamicSharedMemorySize,
                         LSTM_SMEM);

    detect_cap64<<<1, 32>>>((const int*)captions);
    init_state<<<64, 256>>>();
    zero_out0<<<dim3(125, 32), 256>>>(out);
    build_xseq<<<dim3(63, 32), 128>>>(features, captions, embed);

    // pre-gates for all timesteps: [2016,512] @ [512,2048]
    gemm_tf32<0, G4><<<dim3(G4 / 64, 16), 256>>>(W_ih, b_ih, b_hh, nullptr);

    // sequential recurrence
    for (int t = 0; t < NSTEP; t++)
        lstm_step<<<128, 256, LSTM_SMEM>>>(W_hh, t);

    // output projection: [2016,512] @ [512,32000], scattered to out[b][t+1][:]
    gemm_tf32<1, VV><<<dim3(VV / 64, 16), 256>>>(fc_w, fc_b, nullptr, out);
}